// round 13
// baseline (speedup 1.0000x reference)
#include <cuda_runtime.h>
#include <cuda_fp16.h>

#define NMAX 100000
#define EMAX 1600000
#define DIMS 128
#define CAP  128            // fixed bucket capacity per node (Poisson(16) degrees)

// Scratch (allocation-free rule: __device__ globals)
__device__ __half g_xh[(size_t)NMAX * DIMS];     // 25.6 MB fp16 copy of x
__device__ int    g_cursor[NMAX];
__device__ int    g_csr[(size_t)NMAX * CAP];     // 51.2 MB bucketed adjacency

// ---------------------------------------------------------------------------
// Clear cursors
// ---------------------------------------------------------------------------
__global__ void k_clear(int N) {
    int i = blockIdx.x * blockDim.x + threadIdx.x;
    if (i < N) g_cursor[i] = 0;
}

// ---------------------------------------------------------------------------
// Merged convert (x -> fp16 table) || bucket-CSR fill (block-split roles)
// ---------------------------------------------------------------------------
__global__ void k_convert_fill(const float* __restrict__ x,
                               const int* __restrict__ ei,
                               int total4, int E, int N, int BC) {
    if (blockIdx.x < BC) {
        int i = blockIdx.x * blockDim.x + threadIdx.x;
        if (i < total4) {
            float4 v = reinterpret_cast<const float4*>(x)[i];
            __half2 a = __floats2half2_rn(v.x, v.y);
            __half2 b = __floats2half2_rn(v.z, v.w);
            uint2 o;
            o.x = *reinterpret_cast<unsigned*>(&a);
            o.y = *reinterpret_cast<unsigned*>(&b);
            reinterpret_cast<uint2*>(g_xh)[i] = o;
        }
    } else {
        int t = (blockIdx.x - BC) * blockDim.x + threadIdx.x;
        int e0 = t * 4;
        if (e0 + 4 <= E) {
            int4 rows = *reinterpret_cast<const int4*>(ei + e0);
            int4 cols = *reinterpret_cast<const int4*>(ei + E + e0);
            int r[4] = { rows.x, rows.y, rows.z, rows.w };
            int c[4] = { cols.x, cols.y, cols.z, cols.w };
            #pragma unroll
            for (int q = 0; q < 4; q++) {
                if ((unsigned)r[q] < (unsigned)N && (unsigned)c[q] < (unsigned)N) {
                    int pos = atomicAdd(&g_cursor[r[q]], 1);
                    if (pos < CAP) g_csr[(size_t)r[q] * CAP + pos] = c[q];
                }
            }
        } else if (e0 < E) {
            for (int e = e0; e < E; e++) {
                int row = ei[e];
                int col = ei[E + e];
                if ((unsigned)row < (unsigned)N && (unsigned)col < (unsigned)N) {
                    int pos = atomicAdd(&g_cursor[row], 1);
                    if (pos < CAP) g_csr[(size_t)row * CAP + pos] = col;
                }
            }
        }
    }
}

// ---------------------------------------------------------------------------
// FUSED persistent kernel (512 threads, 148 CTAs):
// per 128-row tile:
//   phase 1: 32 half-warps gather-aggregate the tile's 128 nodes (4 each)
//            from g_xh via bucket CSR  ->  fp16 agg tile DIRECTLY in smem
//   phase 2: mma.m16n8k16:  out = relu( [x | agg] @ [W1 | W2]^T )
// x tiles cp.async double-buffered (wait deferred to after the gather);
// weights staged once per CTA (pair-permuted, LDS.64 B-frags).
// ---------------------------------------------------------------------------
#define SH_A 136                     // halves per A row (272B, 16B-aligned rows)
#define SH_W 272
#define SMEM_W_HALVES (128 * SH_W)   // 34816 halves = 69632 B
#define SMEM_A_HALVES (128 * SH_A)   // 17408 halves = 34816 B
// total = 69632 + 2*34816 (x bufs) + 34816 (agg) = 174080 B

__device__ __forceinline__ unsigned pack_h2(float a, float b) {
    __half2 h = __floats2half2_rn(a, b);
    return *reinterpret_cast<unsigned*>(&h);
}

__device__ __forceinline__ __half2 slot_h2(const uint4& v, int s) {
    return *reinterpret_cast<const __half2*>(reinterpret_cast<const unsigned*>(&v.x) + s);
}

__device__ __forceinline__ void mma_fp16(float d[4],
                                         const unsigned a[4],
                                         unsigned b0, unsigned b1) {
    asm volatile(
        "mma.sync.aligned.m16n8k16.row.col.f32.f16.f16.f32 "
        "{%0,%1,%2,%3},{%4,%5,%6,%7},{%8,%9},{%0,%1,%2,%3};"
        : "+f"(d[0]), "+f"(d[1]), "+f"(d[2]), "+f"(d[3])
        : "r"(a[0]), "r"(a[1]), "r"(a[2]), "r"(a[3]), "r"(b0), "r"(b1));
}

__device__ __forceinline__ void cp_async16(__half* smem_dst, const void* gmem_src,
                                           bool valid) {
    unsigned saddr = (unsigned)__cvta_generic_to_shared(smem_dst);
    int sz = valid ? 16 : 0;
    asm volatile("cp.async.cg.shared.global [%0], [%1], 16, %2;\n"
                 :: "r"(saddr), "l"(gmem_src), "r"(sz));
}
__device__ __forceinline__ void cp_commit() {
    asm volatile("cp.async.commit_group;\n");
}
template <int NWAIT>
__device__ __forceinline__ void cp_wait() {
    asm volatile("cp.async.wait_group %0;\n" :: "n"(NWAIT));
}

__global__ void __launch_bounds__(512, 1)
k_fused(const float* __restrict__ W1,
        const float* __restrict__ W2,
        float* __restrict__ out, int N)
{
    extern __shared__ __half sm[];
    __half* sW  = sm;                              // [128][272] pair-permuted
    __half* sX0 = sW + SMEM_W_HALVES;              // x tile buf 0
    __half* sX1 = sX0 + SMEM_A_HALVES;             // x tile buf 1
    __half* sAg = sX1 + SMEM_A_HALVES;             // agg tile (single buffer)

    const int tid    = threadIdx.x;
    const int lane   = tid & 31;
    const int wid    = tid >> 5;     // 0..15
    const int gid    = lane >> 2;    // 0..7
    const int tig    = lane & 3;     // 0..3
    const int warp_m = wid & 3;      // rows 32*warp_m
    const int warp_n = wid >> 2;     // cols 32*warp_n

    const int hw    = tid >> 4;      // half-warp id 0..31
    const int hlane = tid & 15;      // lane in half-warp

    // ---- Stage weights ONCE (fp32 -> fp16, pair-permuted) ----
    {
        const float4* W1_4 = reinterpret_cast<const float4*>(W1);
        const float4* W2_4 = reinterpret_cast<const float4*>(W2);
        #pragma unroll
        for (int idx = tid; idx < 4096; idx += 512) {
            int mtx = idx >> 11;
            int n   = (idx >> 4) & 127;
            int g8  = idx & 15;
            const float4* src = mtx ? W2_4 : W1_4;
            float4 f0 = src[n * 32 + g8 * 2];
            float4 f1 = src[n * 32 + g8 * 2 + 1];
            int kg  = mtx * 128 + g8 * 8;
            int G   = kg >> 4;
            int odd = (kg >> 3) & 1;
            unsigned* dst = reinterpret_cast<unsigned*>(sW + n * SH_W + G * 16 + 2 * odd);
            dst[0] = pack_h2(f0.x, f0.y);
            dst[2] = pack_h2(f0.z, f0.w);
            dst[4] = pack_h2(f1.x, f1.y);
            dst[6] = pack_h2(f1.z, f1.w);
        }
    }

    const uint4* xh4 = reinterpret_cast<const uint4*>(g_xh);   // 16 uint4 / row
    const int ntiles = (N + 127) / 128;

    // stage x tile -> buffer via cp.async.
    // 2048 items = 128 rows * 16 chunks of 16B (8 halves each).  (R12 bug was
    // staging only 8 of the 16 chunks -> half the tile uninitialized.)
    auto stageX = [&](int tile, __half* buf) {
        int row0 = tile * 128;
        #pragma unroll
        for (int i = 0; i < 4; i++) {
            int idx = tid + i * 512;        // 0..2047
            int r   = idx >> 4;             // 0..127
            int g8  = idx & 15;             // 0..15
            int gr  = row0 + r;
            bool v  = (gr < N);
            int grc = v ? gr : 0;
            cp_async16(buf + r * SH_A + g8 * 8,
                       xh4 + (size_t)grc * 16 + g8, v);
        }
    };

    __half* bufs[2] = { sX0, sX1 };
    int t0 = blockIdx.x;
    if (t0 < ntiles) { stageX(t0, bufs[0]); cp_commit(); }

    int b = 0;
    for (int tile = t0; tile < ntiles; tile += gridDim.x, b ^= 1) {
        int nxt = tile + gridDim.x;
        bool have_next = (nxt < ntiles);
        if (have_next) { stageX(nxt, bufs[b ^ 1]); cp_commit(); }

        const int row0 = tile * 128;

        // ===== Phase 1: gather-aggregate this tile's rows into sAg =====
        // (previous iteration's trailing __syncthreads guarantees sAg free)
        #pragma unroll 1
        for (int rr = 0; rr < 4; rr++) {
            int r  = rr * 32 + hw;
            int gr = row0 + r;
            float acc[8];
            #pragma unroll
            for (int s = 0; s < 8; s++) acc[s] = 0.f;

            if (gr < N) {
                int deg = g_cursor[gr];
                if (deg > CAP) deg = CAP;
                const int* list = g_csr + gr * CAP;
                int j = 0;
                for (; j + 4 <= deg; j += 4) {
                    int4 cs = *reinterpret_cast<const int4*>(list + j);
                    uint4 v0 = xh4[(unsigned)cs.x * 16u + (unsigned)hlane];
                    uint4 v1 = xh4[(unsigned)cs.y * 16u + (unsigned)hlane];
                    uint4 v2 = xh4[(unsigned)cs.z * 16u + (unsigned)hlane];
                    uint4 v3 = xh4[(unsigned)cs.w * 16u + (unsigned)hlane];
                    #pragma unroll
                    for (int s = 0; s < 4; s++) {
                        __half2 t = __hadd2(__hadd2(slot_h2(v0, s), slot_h2(v1, s)),
                                            __hadd2(slot_h2(v2, s), slot_h2(v3, s)));
                        float2 f = __half22float2(t);
                        acc[2 * s]     += f.x;
                        acc[2 * s + 1] += f.y;
                    }
                }
                for (; j < deg; j++) {
                    int c = list[j];
                    uint4 v = xh4[(unsigned)c * 16u + (unsigned)hlane];
                    #pragma unroll
                    for (int s = 0; s < 4; s++) {
                        float2 f = __half22float2(slot_h2(v, s));
                        acc[2 * s]     += f.x;
                        acc[2 * s + 1] += f.y;
                    }
                }
            }
            uint4 o;
            unsigned* op = reinterpret_cast<unsigned*>(&o.x);
            #pragma unroll
            for (int s = 0; s < 4; s++)
                op[s] = pack_h2(acc[2 * s], acc[2 * s + 1]);
            *reinterpret_cast<uint4*>(sAg + r * SH_A + hlane * 8) = o;
        }

        // x tile for THIS iteration must be resident now
        if (have_next) cp_wait<1>(); else cp_wait<0>();
        __syncthreads();

        // ===== Phase 2: mma =====
        const __half* bX = bufs[b];

        float d[2][4][4];
        #pragma unroll
        for (int m = 0; m < 2; m++)
            #pragma unroll
            for (int j = 0; j < 4; j++)
                #pragma unroll
                for (int q = 0; q < 4; q++)
                    d[m][j][q] = 0.f;

        #pragma unroll
        for (int ks = 0; ks < 16; ks++) {
            const __half* buf = (ks < 8) ? bX : sAg;
            const int k0 = (ks & 7) * 16;

            unsigned a[2][4];
            #pragma unroll
            for (int m = 0; m < 2; m++) {
                int row = warp_m * 32 + m * 16 + gid;
                const __half* p0 = buf + row * SH_A + k0 + 2 * tig;
                const __half* p1 = buf + (row + 8) * SH_A + k0 + 2 * tig;
                a[m][0] = *reinterpret_cast<const unsigned*>(p0);
                a[m][1] = *reinterpret_cast<const unsigned*>(p1);
                a[m][2] = *reinterpret_cast<const unsigned*>(p0 + 8);
                a[m][3] = *reinterpret_cast<const unsigned*>(p1 + 8);
            }
            unsigned b0[4], b1[4];
            #pragma unroll
            for (int j = 0; j < 4; j++) {
                int n = warp_n * 32 + j * 8 + gid;
                uint2 w = reinterpret_cast<const uint2*>(sW + n * SH_W + ks * 16)[tig];
                b0[j] = w.x;
                b1[j] = w.y;
            }
            #pragma unroll
            for (int m = 0; m < 2; m++)
                #pragma unroll
                for (int j = 0; j < 4; j++)
                    mma_fp16(d[m][j], a[m], b0[j], b1[j]);
        }

        // ---- Epilogue: relu + float2 stores ----
        #pragma unroll
        for (int m = 0; m < 2; m++) {
            int r = row0 + warp_m * 32 + m * 16 + gid;
            #pragma unroll
            for (int j = 0; j < 4; j++) {
                int cbase = warp_n * 32 + j * 8 + tig * 2;
                if (r < N) {
                    float2 o = make_float2(fmaxf(d[m][j][0], 0.f), fmaxf(d[m][j][1], 0.f));
                    *reinterpret_cast<float2*>(out + (size_t)r * 128 + cbase) = o;
                }
                if (r + 8 < N) {
                    float2 o = make_float2(fmaxf(d[m][j][2], 0.f), fmaxf(d[m][j][3], 0.f));
                    *reinterpret_cast<float2*>(out + (size_t)(r + 8) * 128 + cbase) = o;
                }
            }
        }
        __syncthreads();   // sAg + x buf free before next iteration's writes
    }
}

// ---------------------------------------------------------------------------
// Launch
// ---------------------------------------------------------------------------
extern "C" void kernel_launch(void* const* d_in, const int* in_sizes, int n_in,
                              void* d_out, int out_size) {
    const float* x  = (const float*)d_in[0];
    const int*   ei = (const int*)d_in[1];
    const float* W1 = (const float*)d_in[2];
    const float* W2 = (const float*)d_in[3];
    float* out = (float*)d_out;

    int N = in_sizes[0] / DIMS;       // 100000
    int E = in_sizes[1] / 2;          // 1600000

    // clear cursors
    k_clear<<<(N + 255) / 256, 256>>>(N);

    // convert || fill (merged, overlapping)
    {
        int total4 = N * (DIMS / 4);
        int BC = (total4 + 255) / 256;
        int BF = ((E + 3) / 4 + 255) / 256;
        k_convert_fill<<<BC + BF, 256>>>(x, ei, total4, E, N, BC);
    }

    // fused gather-aggregate + fp16 mma GEMM + relu (persistent)
    {
        int smem_bytes = (SMEM_W_HALVES + 3 * SMEM_A_HALVES) * (int)sizeof(__half); // 174080
        cudaFuncSetAttribute(k_fused,
                             cudaFuncAttributeMaxDynamicSharedMemorySize,
                             smem_bytes);
        k_fused<<<148, 512, smem_bytes>>>(W1, W2, out, N);
    }
}

// round 14
// speedup vs baseline: 1.2197x; 1.2197x over previous
#include <cuda_runtime.h>
#include <cuda_fp16.h>

#define NMAX 100000
#define EMAX 1600000
#define DIMS 128
#define CAP  128            // fixed bucket capacity per node (Poisson(16) degrees)

// Scratch (allocation-free rule: __device__ globals; zero-init at module load)
__device__ __half g_xh  [(size_t)NMAX * DIMS];   // 25.6 MB fp16 copy of x
__device__ __half g_aggh[(size_t)NMAX * DIMS];   // 25.6 MB fp16 aggregated x
__device__ int    g_cursor[NMAX];                // zero-init; reset by k_aggregate
__device__ int    g_csr[(size_t)NMAX * CAP];     // 51.2 MB bucketed adjacency

// ---------------------------------------------------------------------------
// Merged convert (x -> fp16 table) || bucket-CSR fill (block-split roles).
// g_cursor is zero at entry: zero-initialized at load, and k_aggregate
// resets it after consuming (so every graph replay sees zeros).
// ---------------------------------------------------------------------------
__global__ void k_convert_fill(const float* __restrict__ x,
                               const int* __restrict__ ei,
                               int total4, int E, int N, int BC) {
    if (blockIdx.x < BC) {
        int i = blockIdx.x * blockDim.x + threadIdx.x;
        if (i < total4) {
            float4 v = reinterpret_cast<const float4*>(x)[i];
            __half2 a = __floats2half2_rn(v.x, v.y);
            __half2 b = __floats2half2_rn(v.z, v.w);
            uint2 o;
            o.x = *reinterpret_cast<unsigned*>(&a);
            o.y = *reinterpret_cast<unsigned*>(&b);
            reinterpret_cast<uint2*>(g_xh)[i] = o;
        }
    } else {
        int t = (blockIdx.x - BC) * blockDim.x + threadIdx.x;
        int e0 = t * 8;
        if (e0 + 8 <= E) {
            int4 r0 = *reinterpret_cast<const int4*>(ei + e0);
            int4 r1 = *reinterpret_cast<const int4*>(ei + e0 + 4);
            int4 c0 = *reinterpret_cast<const int4*>(ei + E + e0);
            int4 c1 = *reinterpret_cast<const int4*>(ei + E + e0 + 4);
            int r[8] = { r0.x, r0.y, r0.z, r0.w, r1.x, r1.y, r1.z, r1.w };
            int c[8] = { c0.x, c0.y, c0.z, c0.w, c1.x, c1.y, c1.z, c1.w };
            #pragma unroll
            for (int q = 0; q < 8; q++) {
                if ((unsigned)r[q] < (unsigned)N && (unsigned)c[q] < (unsigned)N) {
                    int pos = atomicAdd(&g_cursor[r[q]], 1);
                    if (pos < CAP) g_csr[(size_t)r[q] * CAP + pos] = c[q];
                }
            }
        } else if (e0 < E) {
            for (int e = e0; e < E; e++) {
                int row = ei[e];
                int col = ei[E + e];
                if ((unsigned)row < (unsigned)N && (unsigned)col < (unsigned)N) {
                    int pos = atomicAdd(&g_cursor[row], 1);
                    if (pos < CAP) g_csr[(size_t)row * CAP + pos] = col;
                }
            }
        }
    }
}

// ---------------------------------------------------------------------------
// Gather-aggregate: half-warp per node, MLP-8 (two independent 4-trees per
// batch, each flushed to fp32 -> numerics identical to the 4-batch version).
// Resets g_cursor[node] = 0 after reading (prepares next graph replay).
// ---------------------------------------------------------------------------
__device__ __forceinline__ __half2 slot_h2(const uint4& v, int s) {
    return *reinterpret_cast<const __half2*>(reinterpret_cast<const unsigned*>(&v.x) + s);
}

__global__ void k_aggregate(int N) {
    int node = (int)((blockIdx.x * blockDim.x + threadIdx.x) >> 4);
    if (node >= N) return;
    int hlane = threadIdx.x & 15;
    int deg  = g_cursor[node];
    if (deg > CAP) deg = CAP;
    const int* list = g_csr + node * CAP;

    const uint4* xh = reinterpret_cast<const uint4*>(g_xh);   // 16 uint4 / row
    float acc[8];
    #pragma unroll
    for (int s = 0; s < 8; s++) acc[s] = 0.f;

    int j = 0;
    for (; j + 8 <= deg; j += 8) {
        int4 ca = *reinterpret_cast<const int4*>(list + j);
        int4 cb = *reinterpret_cast<const int4*>(list + j + 4);
        uint4 v0 = xh[(unsigned)ca.x * 16u + (unsigned)hlane];
        uint4 v1 = xh[(unsigned)ca.y * 16u + (unsigned)hlane];
        uint4 v2 = xh[(unsigned)ca.z * 16u + (unsigned)hlane];
        uint4 v3 = xh[(unsigned)ca.w * 16u + (unsigned)hlane];
        uint4 v4 = xh[(unsigned)cb.x * 16u + (unsigned)hlane];
        uint4 v5 = xh[(unsigned)cb.y * 16u + (unsigned)hlane];
        uint4 v6 = xh[(unsigned)cb.z * 16u + (unsigned)hlane];
        uint4 v7 = xh[(unsigned)cb.w * 16u + (unsigned)hlane];
        #pragma unroll
        for (int s = 0; s < 4; s++) {
            __half2 ta = __hadd2(__hadd2(slot_h2(v0, s), slot_h2(v1, s)),
                                 __hadd2(slot_h2(v2, s), slot_h2(v3, s)));
            __half2 tb = __hadd2(__hadd2(slot_h2(v4, s), slot_h2(v5, s)),
                                 __hadd2(slot_h2(v6, s), slot_h2(v7, s)));
            float2 fa = __half22float2(ta);
            float2 fb = __half22float2(tb);
            acc[2 * s]     += fa.x + fb.x;
            acc[2 * s + 1] += fa.y + fb.y;
        }
    }
    for (; j + 4 <= deg; j += 4) {
        int4 cs = *reinterpret_cast<const int4*>(list + j);
        uint4 v0 = xh[(unsigned)cs.x * 16u + (unsigned)hlane];
        uint4 v1 = xh[(unsigned)cs.y * 16u + (unsigned)hlane];
        uint4 v2 = xh[(unsigned)cs.z * 16u + (unsigned)hlane];
        uint4 v3 = xh[(unsigned)cs.w * 16u + (unsigned)hlane];
        #pragma unroll
        for (int s = 0; s < 4; s++) {
            __half2 t = __hadd2(__hadd2(slot_h2(v0, s), slot_h2(v1, s)),
                                __hadd2(slot_h2(v2, s), slot_h2(v3, s)));
            float2 f = __half22float2(t);
            acc[2 * s]     += f.x;
            acc[2 * s + 1] += f.y;
        }
    }
    for (; j < deg; j++) {
        int c = list[j];
        uint4 v = xh[(unsigned)c * 16u + (unsigned)hlane];
        #pragma unroll
        for (int s = 0; s < 4; s++) {
            float2 f = __half22float2(slot_h2(v, s));
            acc[2 * s]     += f.x;
            acc[2 * s + 1] += f.y;
        }
    }

    uint4 o;
    unsigned* op = reinterpret_cast<unsigned*>(&o.x);
    #pragma unroll
    for (int s = 0; s < 4; s++) {
        __half2 h = __floats2half2_rn(acc[2 * s], acc[2 * s + 1]);
        op[s] = *reinterpret_cast<unsigned*>(&h);
    }
    reinterpret_cast<uint4*>(g_aggh)[(unsigned)node * 16u + (unsigned)hlane] = o;

    if (hlane == 0) g_cursor[node] = 0;   // ready for next replay
}

// ---------------------------------------------------------------------------
// Persistent FP16 tensor-core GEMM, cp.async pipeline, 512 threads
// (byte-identical to R10's 39.3us version):
//   out = relu( [x | agg] (M x 256, fp16) @ [W1 | W2]^T (256 x 128, fp16) )
// ---------------------------------------------------------------------------
#define SH_A 136
#define SH_W 272
#define SMEM_W_HALVES (128 * SH_W)   // 34816 halves = 69632 B
#define SMEM_A_HALVES (128 * SH_A)   // 17408 halves = 34816 B (per x/agg array)

__device__ __forceinline__ unsigned pack_h2(float a, float b) {
    __half2 h = __floats2half2_rn(a, b);
    return *reinterpret_cast<unsigned*>(&h);
}

__device__ __forceinline__ void mma_fp16(float d[4],
                                         const unsigned a[4],
                                         unsigned b0, unsigned b1) {
    asm volatile(
        "mma.sync.aligned.m16n8k16.row.col.f32.f16.f16.f32 "
        "{%0,%1,%2,%3},{%4,%5,%6,%7},{%8,%9},{%0,%1,%2,%3};"
        : "+f"(d[0]), "+f"(d[1]), "+f"(d[2]), "+f"(d[3])
        : "r"(a[0]), "r"(a[1]), "r"(a[2]), "r"(a[3]), "r"(b0), "r"(b1));
}

__device__ __forceinline__ void cp_async16(__half* smem_dst, const void* gmem_src,
                                           bool valid) {
    unsigned saddr = (unsigned)__cvta_generic_to_shared(smem_dst);
    int sz = valid ? 16 : 0;
    asm volatile("cp.async.cg.shared.global [%0], [%1], 16, %2;\n"
                 :: "r"(saddr), "l"(gmem_src), "r"(sz));
}
__device__ __forceinline__ void cp_commit() {
    asm volatile("cp.async.commit_group;\n");
}
template <int NWAIT>
__device__ __forceinline__ void cp_wait() {
    asm volatile("cp.async.wait_group %0;\n" :: "n"(NWAIT));
}

__global__ void __launch_bounds__(512, 1)
k_mma_gemm(const float* __restrict__ W1,
           const float* __restrict__ W2,
           float* __restrict__ out, int N)
{
    extern __shared__ __half sm[];
    __half* sW = sm;                                   // [128][272] pair-permuted
    __half* sBuf0 = sW + SMEM_W_HALVES;                // buf0: x then agg
    __half* sBuf1 = sBuf0 + 2 * SMEM_A_HALVES;         // buf1: x then agg

    const int tid    = threadIdx.x;
    const int lane   = tid & 31;
    const int wid    = tid >> 5;     // 0..15
    const int gid    = lane >> 2;    // 0..7
    const int tig    = lane & 3;     // 0..3
    const int warp_m = wid & 3;      // rows 32*warp_m
    const int warp_n = wid >> 2;     // cols 32*warp_n (0..3)

    // ---- Stage weights ONCE (fp32 -> fp16, pair-permuted) ----
    {
        const float4* W1_4 = reinterpret_cast<const float4*>(W1);
        const float4* W2_4 = reinterpret_cast<const float4*>(W2);
        #pragma unroll
        for (int idx = tid; idx < 4096; idx += 512) {
            int mtx = idx >> 11;
            int n   = (idx >> 4) & 127;
            int g8  = idx & 15;
            const float4* src = mtx ? W2_4 : W1_4;
            float4 f0 = src[n * 32 + g8 * 2];
            float4 f1 = src[n * 32 + g8 * 2 + 1];
            int kg  = mtx * 128 + g8 * 8;
            int G   = kg >> 4;
            int odd = (kg >> 3) & 1;
            unsigned* dst = reinterpret_cast<unsigned*>(sW + n * SH_W + G * 16 + 2 * odd);
            dst[0] = pack_h2(f0.x, f0.y);
            dst[2] = pack_h2(f0.z, f0.w);
            dst[4] = pack_h2(f1.x, f1.y);
            dst[6] = pack_h2(f1.z, f1.w);
        }
    }

    const uint4* xh4 = reinterpret_cast<const uint4*>(g_xh);   // 16 uint4 / row
    const uint4* ah4 = reinterpret_cast<const uint4*>(g_aggh);
    const int ntiles = (N + 127) / 128;

    auto stage = [&](int tile, __half* buf) {
        int row0 = tile * 128;
        #pragma unroll
        for (int i = 0; i < 4; i++) {
            int idx = tid + i * 512;        // 2048 = 128 rows * 16 chunks
            int r   = idx >> 4;
            int g8  = idx & 15;
            int gr  = row0 + r;
            bool v  = (gr < N);
            int grc = v ? gr : 0;
            cp_async16(buf + r * SH_A + g8 * 8,
                       xh4 + (size_t)grc * 16 + g8, v);
            cp_async16(buf + SMEM_A_HALVES + r * SH_A + g8 * 8,
                       ah4 + (size_t)grc * 16 + g8, v);
        }
    };

    __half* bufs[2] = { sBuf0, sBuf1 };
    int t0 = blockIdx.x;
    if (t0 < ntiles) { stage(t0, bufs[0]); cp_commit(); }

    int b = 0;
    for (int tile = t0; tile < ntiles; tile += gridDim.x, b ^= 1) {
        int nxt = tile + gridDim.x;
        bool have_next = (nxt < ntiles);
        if (have_next) { stage(nxt, bufs[b ^ 1]); cp_commit(); }

        if (have_next) cp_wait<1>(); else cp_wait<0>();
        __syncthreads();

        const __half* bX  = bufs[b];
        const __half* bAg = bufs[b] + SMEM_A_HALVES;
        const int row0 = tile * 128;

        float d[2][4][4];
        #pragma unroll
        for (int m = 0; m < 2; m++)
            #pragma unroll
            for (int j = 0; j < 4; j++)
                #pragma unroll
                for (int q = 0; q < 4; q++)
                    d[m][j][q] = 0.f;

        #pragma unroll
        for (int ks = 0; ks < 16; ks++) {
            const __half* buf = (ks < 8) ? bX : bAg;
            const int k0 = (ks & 7) * 16;

            unsigned a[2][4];
            #pragma unroll
            for (int m = 0; m < 2; m++) {
                int row = warp_m * 32 + m * 16 + gid;
                const __half* p0 = buf + row * SH_A + k0 + 2 * tig;
                const __half* p1 = buf + (row + 8) * SH_A + k0 + 2 * tig;
                a[m][0] = *reinterpret_cast<const unsigned*>(p0);
                a[m][1] = *reinterpret_cast<const unsigned*>(p1);
                a[m][2] = *reinterpret_cast<const unsigned*>(p0 + 8);
                a[m][3] = *reinterpret_cast<const unsigned*>(p1 + 8);
            }
            unsigned b0[4], b1[4];
            #pragma unroll
            for (int j = 0; j < 4; j++) {
                int n = warp_n * 32 + j * 8 + gid;
                uint2 w = reinterpret_cast<const uint2*>(sW + n * SH_W + ks * 16)[tig];
                b0[j] = w.x;
                b1[j] = w.y;
            }
            #pragma unroll
            for (int m = 0; m < 2; m++)
                #pragma unroll
                for (int j = 0; j < 4; j++)
                    mma_fp16(d[m][j], a[m], b0[j], b1[j]);
        }

        // ---- Epilogue: relu + float2 stores ----
        #pragma unroll
        for (int m = 0; m < 2; m++) {
            int r = row0 + warp_m * 32 + m * 16 + gid;
            #pragma unroll
            for (int j = 0; j < 4; j++) {
                int cbase = warp_n * 32 + j * 8 + tig * 2;
                if (r < N) {
                    float2 o = make_float2(fmaxf(d[m][j][0], 0.f), fmaxf(d[m][j][1], 0.f));
                    *reinterpret_cast<float2*>(out + (size_t)r * 128 + cbase) = o;
                }
                if (r + 8 < N) {
                    float2 o = make_float2(fmaxf(d[m][j][2], 0.f), fmaxf(d[m][j][3], 0.f));
                    *reinterpret_cast<float2*>(out + (size_t)(r + 8) * 128 + cbase) = o;
                }
            }
        }
        __syncthreads();   // all warps done reading bufs[b] before restage
    }
}

// ---------------------------------------------------------------------------
// Launch
// ---------------------------------------------------------------------------
extern "C" void kernel_launch(void* const* d_in, const int* in_sizes, int n_in,
                              void* d_out, int out_size) {
    const float* x  = (const float*)d_in[0];
    const int*   ei = (const int*)d_in[1];
    const float* W1 = (const float*)d_in[2];
    const float* W2 = (const float*)d_in[3];
    float* out = (float*)d_out;

    int N = in_sizes[0] / DIMS;       // 100000
    int E = in_sizes[1] / 2;          // 1600000

    // convert || fill (merged; cursors are zero from load-time init or from
    // the previous execution's aggregate reset)
    {
        int total4 = N * (DIMS / 4);
        int BC = (total4 + 255) / 256;
        int BF = ((E + 7) / 8 + 255) / 256;
        k_convert_fill<<<BC + BF, 256>>>(x, ei, total4, E, N, BC);
    }

    // gather-aggregate (half-warp per node, MLP-8) + cursor reset
    {
        size_t threads = (size_t)N * 16;
        int blocks = (int)((threads + 255) / 256);
        k_aggregate<<<blocks, 256>>>(N);
    }

    // persistent fp16 tensor-core GEMM + relu (cp.async pipelined, 512 thr)
    {
        int smem_bytes = (SMEM_W_HALVES + 4 * SMEM_A_HALVES) * (int)sizeof(__half); // 208896
        cudaFuncSetAttribute(k_mma_gemm,
                             cudaFuncAttributeMaxDynamicSharedMemorySize,
                             smem_bytes);
        k_mma_gemm<<<148, 512, smem_bytes>>>(W1, W2, out, N);
    }
}

// round 15
// speedup vs baseline: 1.3163x; 1.0792x over previous
#include <cuda_runtime.h>
#include <cuda_fp16.h>

#define NMAX 100000
#define EMAX 1600000
#define DIMS 128
#define CAP  128            // fixed bucket capacity per node (Poisson(16) degrees)

// Scratch (allocation-free rule: __device__ globals; zero-init at module load)
__device__ __half g_xh  [(size_t)NMAX * DIMS];   // 25.6 MB fp16 copy of x
__device__ __half g_aggh[(size_t)NMAX * DIMS];   // 25.6 MB fp16 aggregated x
__device__ int    g_cursor[NMAX];                // zero-init; reset by k_aggregate
__device__ int    g_csr[(size_t)NMAX * CAP];     // 51.2 MB bucketed adjacency

// ---------------------------------------------------------------------------
// Merged convert (x -> fp16 table) || bucket-CSR fill (block-split roles).
// Fill role: 2 edges/thread -> 800k threads so ATOMG latency is covered.
// g_cursor is zero at entry (load-time init / reset by k_aggregate).
// ---------------------------------------------------------------------------
__global__ void k_convert_fill(const float* __restrict__ x,
                               const int* __restrict__ ei,
                               int total4, int E, int N, int BC) {
    if (blockIdx.x < BC) {
        int i = blockIdx.x * blockDim.x + threadIdx.x;
        if (i < total4) {
            float4 v = reinterpret_cast<const float4*>(x)[i];
            __half2 a = __floats2half2_rn(v.x, v.y);
            __half2 b = __floats2half2_rn(v.z, v.w);
            uint2 o;
            o.x = *reinterpret_cast<unsigned*>(&a);
            o.y = *reinterpret_cast<unsigned*>(&b);
            reinterpret_cast<uint2*>(g_xh)[i] = o;
        }
    } else {
        int t = (blockIdx.x - BC) * blockDim.x + threadIdx.x;
        int e0 = t * 2;
        if (e0 + 2 <= E) {
            int2 rr = *reinterpret_cast<const int2*>(ei + e0);
            int2 cc = *reinterpret_cast<const int2*>(ei + E + e0);
            int r[2] = { rr.x, rr.y };
            int c[2] = { cc.x, cc.y };
            #pragma unroll
            for (int q = 0; q < 2; q++) {
                if ((unsigned)r[q] < (unsigned)N && (unsigned)c[q] < (unsigned)N) {
                    int pos = atomicAdd(&g_cursor[r[q]], 1);
                    if (pos < CAP) g_csr[(size_t)r[q] * CAP + pos] = c[q];
                }
            }
        } else if (e0 < E) {
            for (int e = e0; e < E; e++) {
                int row = ei[e];
                int col = ei[E + e];
                if ((unsigned)row < (unsigned)N && (unsigned)col < (unsigned)N) {
                    int pos = atomicAdd(&g_cursor[row], 1);
                    if (pos < CAP) g_csr[(size_t)row * CAP + pos] = col;
                }
            }
        }
    }
}

// ---------------------------------------------------------------------------
// Gather-aggregate: half-warp per node, MLP-8 (unchanged from R14).
// Resets g_cursor[node] = 0 after reading (prepares next graph replay).
// ---------------------------------------------------------------------------
__device__ __forceinline__ __half2 slot_h2(const uint4& v, int s) {
    return *reinterpret_cast<const __half2*>(reinterpret_cast<const unsigned*>(&v.x) + s);
}

__global__ void k_aggregate(int N) {
    int node = (int)((blockIdx.x * blockDim.x + threadIdx.x) >> 4);
    if (node >= N) return;
    int hlane = threadIdx.x & 15;
    int deg  = g_cursor[node];
    if (deg > CAP) deg = CAP;
    const int* list = g_csr + node * CAP;

    const uint4* xh = reinterpret_cast<const uint4*>(g_xh);   // 16 uint4 / row
    float acc[8];
    #pragma unroll
    for (int s = 0; s < 8; s++) acc[s] = 0.f;

    int j = 0;
    for (; j + 8 <= deg; j += 8) {
        int4 ca = *reinterpret_cast<const int4*>(list + j);
        int4 cb = *reinterpret_cast<const int4*>(list + j + 4);
        uint4 v0 = xh[(unsigned)ca.x * 16u + (unsigned)hlane];
        uint4 v1 = xh[(unsigned)ca.y * 16u + (unsigned)hlane];
        uint4 v2 = xh[(unsigned)ca.z * 16u + (unsigned)hlane];
        uint4 v3 = xh[(unsigned)ca.w * 16u + (unsigned)hlane];
        uint4 v4 = xh[(unsigned)cb.x * 16u + (unsigned)hlane];
        uint4 v5 = xh[(unsigned)cb.y * 16u + (unsigned)hlane];
        uint4 v6 = xh[(unsigned)cb.z * 16u + (unsigned)hlane];
        uint4 v7 = xh[(unsigned)cb.w * 16u + (unsigned)hlane];
        #pragma unroll
        for (int s = 0; s < 4; s++) {
            __half2 ta = __hadd2(__hadd2(slot_h2(v0, s), slot_h2(v1, s)),
                                 __hadd2(slot_h2(v2, s), slot_h2(v3, s)));
            __half2 tb = __hadd2(__hadd2(slot_h2(v4, s), slot_h2(v5, s)),
                                 __hadd2(slot_h2(v6, s), slot_h2(v7, s)));
            float2 fa = __half22float2(ta);
            float2 fb = __half22float2(tb);
            acc[2 * s]     += fa.x + fb.x;
            acc[2 * s + 1] += fa.y + fb.y;
        }
    }
    for (; j + 4 <= deg; j += 4) {
        int4 cs = *reinterpret_cast<const int4*>(list + j);
        uint4 v0 = xh[(unsigned)cs.x * 16u + (unsigned)hlane];
        uint4 v1 = xh[(unsigned)cs.y * 16u + (unsigned)hlane];
        uint4 v2 = xh[(unsigned)cs.z * 16u + (unsigned)hlane];
        uint4 v3 = xh[(unsigned)cs.w * 16u + (unsigned)hlane];
        #pragma unroll
        for (int s = 0; s < 4; s++) {
            __half2 t = __hadd2(__hadd2(slot_h2(v0, s), slot_h2(v1, s)),
                                __hadd2(slot_h2(v2, s), slot_h2(v3, s)));
            float2 f = __half22float2(t);
            acc[2 * s]     += f.x;
            acc[2 * s + 1] += f.y;
        }
    }
    for (; j < deg; j++) {
        int c = list[j];
        uint4 v = xh[(unsigned)c * 16u + (unsigned)hlane];
        #pragma unroll
        for (int s = 0; s < 4; s++) {
            float2 f = __half22float2(slot_h2(v, s));
            acc[2 * s]     += f.x;
            acc[2 * s + 1] += f.y;
        }
    }

    uint4 o;
    unsigned* op = reinterpret_cast<unsigned*>(&o.x);
    #pragma unroll
    for (int s = 0; s < 4; s++) {
        __half2 h = __floats2half2_rn(acc[2 * s], acc[2 * s + 1]);
        op[s] = *reinterpret_cast<unsigned*>(&h);
    }
    reinterpret_cast<uint4*>(g_aggh)[(unsigned)node * 16u + (unsigned)hlane] = o;

    if (hlane == 0) g_cursor[node] = 0;   // ready for next replay
}

// ---------------------------------------------------------------------------
// Persistent FP16 tensor-core GEMM, cp.async pipeline, 512 threads.
// A-fragments loaded via ldmatrix.m8n8.x4 (2 per ks instead of 8 LDS.32):
//   matrix0=(rows0-7,k0-7) matrix1=(rows8-15,k0-7)
//   matrix2=(rows0-7,k8-15) matrix3=(rows8-15,k8-15)  -> a0..a3 of m16n8k16.
// Per-lane address: row = base + (lane&15), k += (lane>>4)*8.
// 272B row stride -> 8 rows hit banks {0,4,...,28}: conflict-free.
// B stays pair-permuted LDS.64.
// ---------------------------------------------------------------------------
#define SH_A 136
#define SH_W 272
#define SMEM_W_HALVES (128 * SH_W)   // 34816 halves = 69632 B
#define SMEM_A_HALVES (128 * SH_A)   // 17408 halves = 34816 B (per x/agg array)

__device__ __forceinline__ unsigned pack_h2(float a, float b) {
    __half2 h = __floats2half2_rn(a, b);
    return *reinterpret_cast<unsigned*>(&h);
}

__device__ __forceinline__ void mma_fp16(float d[4],
                                         const unsigned a[4],
                                         unsigned b0, unsigned b1) {
    asm volatile(
        "mma.sync.aligned.m16n8k16.row.col.f32.f16.f16.f32 "
        "{%0,%1,%2,%3},{%4,%5,%6,%7},{%8,%9},{%0,%1,%2,%3};"
        : "+f"(d[0]), "+f"(d[1]), "+f"(d[2]), "+f"(d[3])
        : "r"(a[0]), "r"(a[1]), "r"(a[2]), "r"(a[3]), "r"(b0), "r"(b1));
}

__device__ __forceinline__ void ldmatrix_x4(unsigned a[4], unsigned saddr) {
    asm volatile(
        "ldmatrix.sync.aligned.m8n8.x4.shared.b16 {%0,%1,%2,%3}, [%4];"
        : "=r"(a[0]), "=r"(a[1]), "=r"(a[2]), "=r"(a[3])
        : "r"(saddr));
}

__device__ __forceinline__ void cp_async16(__half* smem_dst, const void* gmem_src,
                                           bool valid) {
    unsigned saddr = (unsigned)__cvta_generic_to_shared(smem_dst);
    int sz = valid ? 16 : 0;
    asm volatile("cp.async.cg.shared.global [%0], [%1], 16, %2;\n"
                 :: "r"(saddr), "l"(gmem_src), "r"(sz));
}
__device__ __forceinline__ void cp_commit() {
    asm volatile("cp.async.commit_group;\n");
}
template <int NWAIT>
__device__ __forceinline__ void cp_wait() {
    asm volatile("cp.async.wait_group %0;\n" :: "n"(NWAIT));
}

__global__ void __launch_bounds__(512, 1)
k_mma_gemm(const float* __restrict__ W1,
           const float* __restrict__ W2,
           float* __restrict__ out, int N)
{
    extern __shared__ __half sm[];
    __half* sW = sm;                                   // [128][272] pair-permuted
    __half* sBuf0 = sW + SMEM_W_HALVES;                // buf0: x then agg
    __half* sBuf1 = sBuf0 + 2 * SMEM_A_HALVES;         // buf1: x then agg

    const int tid    = threadIdx.x;
    const int lane   = tid & 31;
    const int wid    = tid >> 5;     // 0..15
    const int gid    = lane >> 2;    // 0..7
    const int tig    = lane & 3;     // 0..3
    const int warp_m = wid & 3;      // rows 32*warp_m
    const int warp_n = wid >> 2;     // cols 32*warp_n (0..3)
    const int lrow   = lane & 15;    // ldmatrix row within 16
    const int lkoff  = (lane >> 4) << 3;  // ldmatrix k offset (0 or 8 halves)

    // ---- Stage weights ONCE (fp32 -> fp16, pair-permuted) ----
    {
        const float4* W1_4 = reinterpret_cast<const float4*>(W1);
        const float4* W2_4 = reinterpret_cast<const float4*>(W2);
        #pragma unroll
        for (int idx = tid; idx < 4096; idx += 512) {
            int mtx = idx >> 11;
            int n   = (idx >> 4) & 127;
            int g8  = idx & 15;
            const float4* src = mtx ? W2_4 : W1_4;
            float4 f0 = src[n * 32 + g8 * 2];
            float4 f1 = src[n * 32 + g8 * 2 + 1];
            int kg  = mtx * 128 + g8 * 8;
            int G   = kg >> 4;
            int odd = (kg >> 3) & 1;
            unsigned* dst = reinterpret_cast<unsigned*>(sW + n * SH_W + G * 16 + 2 * odd);
            dst[0] = pack_h2(f0.x, f0.y);
            dst[2] = pack_h2(f0.z, f0.w);
            dst[4] = pack_h2(f1.x, f1.y);
            dst[6] = pack_h2(f1.z, f1.w);
        }
    }

    const uint4* xh4 = reinterpret_cast<const uint4*>(g_xh);   // 16 uint4 / row
    const uint4* ah4 = reinterpret_cast<const uint4*>(g_aggh);
    const int ntiles = (N + 127) / 128;

    auto stage = [&](int tile, __half* buf) {
        int row0 = tile * 128;
        #pragma unroll
        for (int i = 0; i < 4; i++) {
            int idx = tid + i * 512;        // 2048 = 128 rows * 16 chunks
            int r   = idx >> 4;
            int g8  = idx & 15;
            int gr  = row0 + r;
            bool v  = (gr < N);
            int grc = v ? gr : 0;
            cp_async16(buf + r * SH_A + g8 * 8,
                       xh4 + (size_t)grc * 16 + g8, v);
            cp_async16(buf + SMEM_A_HALVES + r * SH_A + g8 * 8,
                       ah4 + (size_t)grc * 16 + g8, v);
        }
    };

    __half* bufs[2] = { sBuf0, sBuf1 };
    int t0 = blockIdx.x;
    if (t0 < ntiles) { stage(t0, bufs[0]); cp_commit(); }

    int b = 0;
    for (int tile = t0; tile < ntiles; tile += gridDim.x, b ^= 1) {
        int nxt = tile + gridDim.x;
        bool have_next = (nxt < ntiles);
        if (have_next) { stage(nxt, bufs[b ^ 1]); cp_commit(); }

        if (have_next) cp_wait<1>(); else cp_wait<0>();
        __syncthreads();

        const __half* bX  = bufs[b];
        const __half* bAg = bufs[b] + SMEM_A_HALVES;
        const int row0 = tile * 128;

        float d[2][4][4];
        #pragma unroll
        for (int m = 0; m < 2; m++)
            #pragma unroll
            for (int j = 0; j < 4; j++)
                #pragma unroll
                for (int q = 0; q < 4; q++)
                    d[m][j][q] = 0.f;

        #pragma unroll
        for (int ks = 0; ks < 16; ks++) {
            const __half* buf = (ks < 8) ? bX : bAg;
            const int k0 = (ks & 7) * 16;

            unsigned a[2][4];
            #pragma unroll
            for (int m = 0; m < 2; m++) {
                int rowA = warp_m * 32 + m * 16 + lrow;
                unsigned sa = (unsigned)__cvta_generic_to_shared(
                    buf + rowA * SH_A + k0 + lkoff);
                ldmatrix_x4(a[m], sa);
            }
            unsigned b0[4], b1[4];
            #pragma unroll
            for (int j = 0; j < 4; j++) {
                int n = warp_n * 32 + j * 8 + gid;
                uint2 w = reinterpret_cast<const uint2*>(sW + n * SH_W + ks * 16)[tig];
                b0[j] = w.x;
                b1[j] = w.y;
            }
            #pragma unroll
            for (int m = 0; m < 2; m++)
                #pragma unroll
                for (int j = 0; j < 4; j++)
                    mma_fp16(d[m][j], a[m], b0[j], b1[j]);
        }

        // ---- Epilogue: relu + float2 stores ----
        #pragma unroll
        for (int m = 0; m < 2; m++) {
            int r = row0 + warp_m * 32 + m * 16 + gid;
            #pragma unroll
            for (int j = 0; j < 4; j++) {
                int cbase = warp_n * 32 + j * 8 + tig * 2;
                if (r < N) {
                    float2 o = make_float2(fmaxf(d[m][j][0], 0.f), fmaxf(d[m][j][1], 0.f));
                    *reinterpret_cast<float2*>(out + (size_t)r * 128 + cbase) = o;
                }
                if (r + 8 < N) {
                    float2 o = make_float2(fmaxf(d[m][j][2], 0.f), fmaxf(d[m][j][3], 0.f));
                    *reinterpret_cast<float2*>(out + (size_t)(r + 8) * 128 + cbase) = o;
                }
            }
        }
        __syncthreads();   // all warps done reading bufs[b] before restage
    }
}

// ---------------------------------------------------------------------------
// Launch
// ---------------------------------------------------------------------------
extern "C" void kernel_launch(void* const* d_in, const int* in_sizes, int n_in,
                              void* d_out, int out_size) {
    const float* x  = (const float*)d_in[0];
    const int*   ei = (const int*)d_in[1];
    const float* W1 = (const float*)d_in[2];
    const float* W2 = (const float*)d_in[3];
    float* out = (float*)d_out;

    int N = in_sizes[0] / DIMS;       // 100000
    int E = in_sizes[1] / 2;          // 1600000

    // convert || fill (merged; fill = 2 edges/thread for latency coverage)
    {
        int total4 = N * (DIMS / 4);
        int BC = (total4 + 255) / 256;
        int BF = ((E + 1) / 2 + 255) / 256;
        k_convert_fill<<<BC + BF, 256>>>(x, ei, total4, E, N, BC);
    }

    // gather-aggregate (half-warp per node, MLP-8) + cursor reset
    {
        size_t threads = (size_t)N * 16;
        int blocks = (int)((threads + 255) / 256);
        k_aggregate<<<blocks, 256>>>(N);
    }

    // persistent fp16 tensor-core GEMM + relu (cp.async + ldmatrix, 512 thr)
    {
        int smem_bytes = (SMEM_W_HALVES + 4 * SMEM_A_HALVES) * (int)sizeof(__half); // 208896
        cudaFuncSetAttribute(k_mma_gemm,
                             cudaFuncAttributeMaxDynamicSharedMemorySize,
                             smem_bytes);
        k_mma_gemm<<<148, 512, smem_bytes>>>(W1, W2, out, N);
    }
}

// round 16
// speedup vs baseline: 1.3675x; 1.0389x over previous
#include <cuda_runtime.h>
#include <cuda_fp16.h>

#define NMAX 100000
#define EMAX 1600000
#define DIMS 128
#define CAP  128            // fixed bucket capacity per node (Poisson(16) degrees)

// Scratch (allocation-free rule: __device__ globals; zero-init at module load)
__device__ __half g_xh  [(size_t)NMAX * DIMS];   // 25.6 MB fp16 copy of x
__device__ __half g_aggh[(size_t)NMAX * DIMS];   // 25.6 MB fp16 aggregated x
__device__ int    g_cursor[NMAX];                // zero-init; reset by k_aggregate
__device__ int    g_csr[(size_t)NMAX * CAP];     // 51.2 MB bucketed adjacency

// ---------------------------------------------------------------------------
// Merged fill || convert. Fill blocks take LOW blockIdx (long atomic chains
// start in wave 0); convert blocks follow. Both roles are MLP-4:
//   fill:    4 edges/thread, int4 batch loads -> 4 independent ATOMG chains
//   convert: 4 float4/thread -> 4 independent LDG.128 in flight
// ---------------------------------------------------------------------------
__global__ void k_fill_convert(const float* __restrict__ x,
                               const int* __restrict__ ei,
                               int total4, int E, int N, int BF) {
    if (blockIdx.x < BF) {
        int t = blockIdx.x * blockDim.x + threadIdx.x;
        int e0 = t * 4;
        if (e0 + 4 <= E) {
            int4 rows = *reinterpret_cast<const int4*>(ei + e0);
            int4 cols = *reinterpret_cast<const int4*>(ei + E + e0);
            int r[4] = { rows.x, rows.y, rows.z, rows.w };
            int c[4] = { cols.x, cols.y, cols.z, cols.w };
            #pragma unroll
            for (int q = 0; q < 4; q++) {
                if ((unsigned)r[q] < (unsigned)N && (unsigned)c[q] < (unsigned)N) {
                    int pos = atomicAdd(&g_cursor[r[q]], 1);
                    if (pos < CAP) g_csr[(size_t)r[q] * CAP + pos] = c[q];
                }
            }
        } else if (e0 < E) {
            for (int e = e0; e < E; e++) {
                int row = ei[e];
                int col = ei[E + e];
                if ((unsigned)row < (unsigned)N && (unsigned)col < (unsigned)N) {
                    int pos = atomicAdd(&g_cursor[row], 1);
                    if (pos < CAP) g_csr[(size_t)row * CAP + pos] = col;
                }
            }
        }
    } else {
        // convert: 4 float4 per thread, coalesced (tid-contiguous per batch)
        int base = (blockIdx.x - BF) * (blockDim.x * 4) + threadIdx.x;
        const float4* xs = reinterpret_cast<const float4*>(x);
        uint2* dst = reinterpret_cast<uint2*>(g_xh);
        float4 v[4];
        bool ok[4];
        #pragma unroll
        for (int q = 0; q < 4; q++) {
            int i = base + q * 256;
            ok[q] = (i < total4);
            if (ok[q]) v[q] = xs[i];
        }
        #pragma unroll
        for (int q = 0; q < 4; q++) {
            if (ok[q]) {
                __half2 a = __floats2half2_rn(v[q].x, v[q].y);
                __half2 b = __floats2half2_rn(v[q].z, v[q].w);
                uint2 o;
                o.x = *reinterpret_cast<unsigned*>(&a);
                o.y = *reinterpret_cast<unsigned*>(&b);
                dst[base + q * 256] = o;
            }
        }
    }
}

// ---------------------------------------------------------------------------
// Gather-aggregate: half-warp per node, MLP-8 (unchanged).
// Resets g_cursor[node] = 0 after reading (prepares next graph replay).
// ---------------------------------------------------------------------------
__device__ __forceinline__ __half2 slot_h2(const uint4& v, int s) {
    return *reinterpret_cast<const __half2*>(reinterpret_cast<const unsigned*>(&v.x) + s);
}

__global__ void k_aggregate(int N) {
    int node = (int)((blockIdx.x * blockDim.x + threadIdx.x) >> 4);
    if (node >= N) return;
    int hlane = threadIdx.x & 15;
    int deg  = g_cursor[node];
    if (deg > CAP) deg = CAP;
    const int* list = g_csr + node * CAP;

    const uint4* xh = reinterpret_cast<const uint4*>(g_xh);   // 16 uint4 / row
    float acc[8];
    #pragma unroll
    for (int s = 0; s < 8; s++) acc[s] = 0.f;

    int j = 0;
    for (; j + 8 <= deg; j += 8) {
        int4 ca = *reinterpret_cast<const int4*>(list + j);
        int4 cb = *reinterpret_cast<const int4*>(list + j + 4);
        uint4 v0 = xh[(unsigned)ca.x * 16u + (unsigned)hlane];
        uint4 v1 = xh[(unsigned)ca.y * 16u + (unsigned)hlane];
        uint4 v2 = xh[(unsigned)ca.z * 16u + (unsigned)hlane];
        uint4 v3 = xh[(unsigned)ca.w * 16u + (unsigned)hlane];
        uint4 v4 = xh[(unsigned)cb.x * 16u + (unsigned)hlane];
        uint4 v5 = xh[(unsigned)cb.y * 16u + (unsigned)hlane];
        uint4 v6 = xh[(unsigned)cb.z * 16u + (unsigned)hlane];
        uint4 v7 = xh[(unsigned)cb.w * 16u + (unsigned)hlane];
        #pragma unroll
        for (int s = 0; s < 4; s++) {
            __half2 ta = __hadd2(__hadd2(slot_h2(v0, s), slot_h2(v1, s)),
                                 __hadd2(slot_h2(v2, s), slot_h2(v3, s)));
            __half2 tb = __hadd2(__hadd2(slot_h2(v4, s), slot_h2(v5, s)),
                                 __hadd2(slot_h2(v6, s), slot_h2(v7, s)));
            float2 fa = __half22float2(ta);
            float2 fb = __half22float2(tb);
            acc[2 * s]     += fa.x + fb.x;
            acc[2 * s + 1] += fa.y + fb.y;
        }
    }
    for (; j + 4 <= deg; j += 4) {
        int4 cs = *reinterpret_cast<const int4*>(list + j);
        uint4 v0 = xh[(unsigned)cs.x * 16u + (unsigned)hlane];
        uint4 v1 = xh[(unsigned)cs.y * 16u + (unsigned)hlane];
        uint4 v2 = xh[(unsigned)cs.z * 16u + (unsigned)hlane];
        uint4 v3 = xh[(unsigned)cs.w * 16u + (unsigned)hlane];
        #pragma unroll
        for (int s = 0; s < 4; s++) {
            __half2 t = __hadd2(__hadd2(slot_h2(v0, s), slot_h2(v1, s)),
                                __hadd2(slot_h2(v2, s), slot_h2(v3, s)));
            float2 f = __half22float2(t);
            acc[2 * s]     += f.x;
            acc[2 * s + 1] += f.y;
        }
    }
    for (; j < deg; j++) {
        int c = list[j];
        uint4 v = xh[(unsigned)c * 16u + (unsigned)hlane];
        #pragma unroll
        for (int s = 0; s < 4; s++) {
            float2 f = __half22float2(slot_h2(v, s));
            acc[2 * s]     += f.x;
            acc[2 * s + 1] += f.y;
        }
    }

    uint4 o;
    unsigned* op = reinterpret_cast<unsigned*>(&o.x);
    #pragma unroll
    for (int s = 0; s < 4; s++) {
        __half2 h = __floats2half2_rn(acc[2 * s], acc[2 * s + 1]);
        op[s] = *reinterpret_cast<unsigned*>(&h);
    }
    reinterpret_cast<uint4*>(g_aggh)[(unsigned)node * 16u + (unsigned)hlane] = o;

    if (hlane == 0) g_cursor[node] = 0;   // ready for next replay
}

// ---------------------------------------------------------------------------
// Persistent FP16 tensor-core GEMM (unchanged from R15):
// cp.async pipeline, 512 threads, ldmatrix.x4 A-frags, pair-permuted B.
// ---------------------------------------------------------------------------
#define SH_A 136
#define SH_W 272
#define SMEM_W_HALVES (128 * SH_W)   // 34816 halves = 69632 B
#define SMEM_A_HALVES (128 * SH_A)   // 17408 halves = 34816 B (per x/agg array)

__device__ __forceinline__ unsigned pack_h2(float a, float b) {
    __half2 h = __floats2half2_rn(a, b);
    return *reinterpret_cast<unsigned*>(&h);
}

__device__ __forceinline__ void mma_fp16(float d[4],
                                         const unsigned a[4],
                                         unsigned b0, unsigned b1) {
    asm volatile(
        "mma.sync.aligned.m16n8k16.row.col.f32.f16.f16.f32 "
        "{%0,%1,%2,%3},{%4,%5,%6,%7},{%8,%9},{%0,%1,%2,%3};"
        : "+f"(d[0]), "+f"(d[1]), "+f"(d[2]), "+f"(d[3])
        : "r"(a[0]), "r"(a[1]), "r"(a[2]), "r"(a[3]), "r"(b0), "r"(b1));
}

__device__ __forceinline__ void ldmatrix_x4(unsigned a[4], unsigned saddr) {
    asm volatile(
        "ldmatrix.sync.aligned.m8n8.x4.shared.b16 {%0,%1,%2,%3}, [%4];"
        : "=r"(a[0]), "=r"(a[1]), "=r"(a[2]), "=r"(a[3])
        : "r"(saddr));
}

__device__ __forceinline__ void cp_async16(__half* smem_dst, const void* gmem_src,
                                           bool valid) {
    unsigned saddr = (unsigned)__cvta_generic_to_shared(smem_dst);
    int sz = valid ? 16 : 0;
    asm volatile("cp.async.cg.shared.global [%0], [%1], 16, %2;\n"
                 :: "r"(saddr), "l"(gmem_src), "r"(sz));
}
__device__ __forceinline__ void cp_commit() {
    asm volatile("cp.async.commit_group;\n");
}
template <int NWAIT>
__device__ __forceinline__ void cp_wait() {
    asm volatile("cp.async.wait_group %0;\n" :: "n"(NWAIT));
}

__global__ void __launch_bounds__(512, 1)
k_mma_gemm(const float* __restrict__ W1,
           const float* __restrict__ W2,
           float* __restrict__ out, int N)
{
    extern __shared__ __half sm[];
    __half* sW = sm;                                   // [128][272] pair-permuted
    __half* sBuf0 = sW + SMEM_W_HALVES;                // buf0: x then agg
    __half* sBuf1 = sBuf0 + 2 * SMEM_A_HALVES;         // buf1: x then agg

    const int tid    = threadIdx.x;
    const int lane   = tid & 31;
    const int wid    = tid >> 5;     // 0..15
    const int gid    = lane >> 2;    // 0..7
    const int tig    = lane & 3;     // 0..3
    const int warp_m = wid & 3;      // rows 32*warp_m
    const int warp_n = wid >> 2;     // cols 32*warp_n (0..3)
    const int lrow   = lane & 15;    // ldmatrix row within 16
    const int lkoff  = (lane >> 4) << 3;  // ldmatrix k offset (0 or 8 halves)

    // ---- Stage weights ONCE (fp32 -> fp16, pair-permuted) ----
    {
        const float4* W1_4 = reinterpret_cast<const float4*>(W1);
        const float4* W2_4 = reinterpret_cast<const float4*>(W2);
        #pragma unroll
        for (int idx = tid; idx < 4096; idx += 512) {
            int mtx = idx >> 11;
            int n   = (idx >> 4) & 127;
            int g8  = idx & 15;
            const float4* src = mtx ? W2_4 : W1_4;
            float4 f0 = src[n * 32 + g8 * 2];
            float4 f1 = src[n * 32 + g8 * 2 + 1];
            int kg  = mtx * 128 + g8 * 8;
            int G   = kg >> 4;
            int odd = (kg >> 3) & 1;
            unsigned* dst = reinterpret_cast<unsigned*>(sW + n * SH_W + G * 16 + 2 * odd);
            dst[0] = pack_h2(f0.x, f0.y);
            dst[2] = pack_h2(f0.z, f0.w);
            dst[4] = pack_h2(f1.x, f1.y);
            dst[6] = pack_h2(f1.z, f1.w);
        }
    }

    const uint4* xh4 = reinterpret_cast<const uint4*>(g_xh);   // 16 uint4 / row
    const uint4* ah4 = reinterpret_cast<const uint4*>(g_aggh);
    const int ntiles = (N + 127) / 128;

    auto stage = [&](int tile, __half* buf) {
        int row0 = tile * 128;
        #pragma unroll
        for (int i = 0; i < 4; i++) {
            int idx = tid + i * 512;        // 2048 = 128 rows * 16 chunks
            int r   = idx >> 4;
            int g8  = idx & 15;
            int gr  = row0 + r;
            bool v  = (gr < N);
            int grc = v ? gr : 0;
            cp_async16(buf + r * SH_A + g8 * 8,
                       xh4 + (size_t)grc * 16 + g8, v);
            cp_async16(buf + SMEM_A_HALVES + r * SH_A + g8 * 8,
                       ah4 + (size_t)grc * 16 + g8, v);
        }
    };

    __half* bufs[2] = { sBuf0, sBuf1 };
    int t0 = blockIdx.x;
    if (t0 < ntiles) { stage(t0, bufs[0]); cp_commit(); }

    int b = 0;
    for (int tile = t0; tile < ntiles; tile += gridDim.x, b ^= 1) {
        int nxt = tile + gridDim.x;
        bool have_next = (nxt < ntiles);
        if (have_next) { stage(nxt, bufs[b ^ 1]); cp_commit(); }

        if (have_next) cp_wait<1>(); else cp_wait<0>();
        __syncthreads();

        const __half* bX  = bufs[b];
        const __half* bAg = bufs[b] + SMEM_A_HALVES;
        const int row0 = tile * 128;

        float d[2][4][4];
        #pragma unroll
        for (int m = 0; m < 2; m++)
            #pragma unroll
            for (int j = 0; j < 4; j++)
                #pragma unroll
                for (int q = 0; q < 4; q++)
                    d[m][j][q] = 0.f;

        #pragma unroll
        for (int ks = 0; ks < 16; ks++) {
            const __half* buf = (ks < 8) ? bX : bAg;
            const int k0 = (ks & 7) * 16;

            unsigned a[2][4];
            #pragma unroll
            for (int m = 0; m < 2; m++) {
                int rowA = warp_m * 32 + m * 16 + lrow;
                unsigned sa = (unsigned)__cvta_generic_to_shared(
                    buf + rowA * SH_A + k0 + lkoff);
                ldmatrix_x4(a[m], sa);
            }
            unsigned b0[4], b1[4];
            #pragma unroll
            for (int j = 0; j < 4; j++) {
                int n = warp_n * 32 + j * 8 + gid;
                uint2 w = reinterpret_cast<const uint2*>(sW + n * SH_W + ks * 16)[tig];
                b0[j] = w.x;
                b1[j] = w.y;
            }
            #pragma unroll
            for (int m = 0; m < 2; m++)
                #pragma unroll
                for (int j = 0; j < 4; j++)
                    mma_fp16(d[m][j], a[m], b0[j], b1[j]);
        }

        // ---- Epilogue: relu + float2 stores ----
        #pragma unroll
        for (int m = 0; m < 2; m++) {
            int r = row0 + warp_m * 32 + m * 16 + gid;
            #pragma unroll
            for (int j = 0; j < 4; j++) {
                int cbase = warp_n * 32 + j * 8 + tig * 2;
                if (r < N) {
                    float2 o = make_float2(fmaxf(d[m][j][0], 0.f), fmaxf(d[m][j][1], 0.f));
                    *reinterpret_cast<float2*>(out + (size_t)r * 128 + cbase) = o;
                }
                if (r + 8 < N) {
                    float2 o = make_float2(fmaxf(d[m][j][2], 0.f), fmaxf(d[m][j][3], 0.f));
                    *reinterpret_cast<float2*>(out + (size_t)(r + 8) * 128 + cbase) = o;
                }
            }
        }
        __syncthreads();   // all warps done reading bufs[b] before restage
    }
}

// ---------------------------------------------------------------------------
// Launch
// ---------------------------------------------------------------------------
extern "C" void kernel_launch(void* const* d_in, const int* in_sizes, int n_in,
                              void* d_out, int out_size) {
    const float* x  = (const float*)d_in[0];
    const int*   ei = (const int*)d_in[1];
    const float* W1 = (const float*)d_in[2];
    const float* W2 = (const float*)d_in[3];
    float* out = (float*)d_out;

    int N = in_sizes[0] / DIMS;       // 100000
    int E = in_sizes[1] / 2;          // 1600000

    // fill || convert (merged; fill blocks first, both roles MLP-4)
    {
        int total4 = N * (DIMS / 4);                       // 3.2M float4
        int BF = ((E + 3) / 4 + 255) / 256;                // fill blocks (1563)
        int BC = (total4 + 1023) / 1024;                   // convert blocks (3125)
        k_fill_convert<<<BF + BC, 256>>>(x, ei, total4, E, N, BF);
    }

    // gather-aggregate (half-warp per node, MLP-8) + cursor reset
    {
        size_t threads = (size_t)N * 16;
        int blocks = (int)((threads + 255) / 256);
        k_aggregate<<<blocks, 256>>>(N);
    }

    // persistent fp16 tensor-core GEMM + relu (cp.async + ldmatrix, 512 thr)
    {
        int smem_bytes = (SMEM_W_HALVES + 4 * SMEM_A_HALVES) * (int)sizeof(__half); // 208896
        cudaFuncSetAttribute(k_mma_gemm,
                             cudaFuncAttributeMaxDynamicSharedMemorySize,
                             smem_bytes);
        k_mma_gemm<<<148, 512, smem_bytes>>>(W1, W2, out, N);
    }
}

// round 17
// speedup vs baseline: 1.3979x; 1.0222x over previous
#include <cuda_runtime.h>
#include <cuda_fp16.h>

#define NMAX 100000
#define EMAX 1600000
#define DIMS 128
#define CAP  128            // fixed bucket capacity per node (Poisson(16) degrees)

// Scratch (allocation-free rule: __device__ globals; zero-init at module load)
__device__ __half g_xh  [(size_t)NMAX * DIMS];   // 25.6 MB fp16 copy of x
__device__ __half g_aggh[(size_t)NMAX * DIMS];   // 25.6 MB fp16 aggregated x
__device__ int    g_cursor[NMAX];                // zero-init; reset by k_aggregate
__device__ int    g_csr[(size_t)NMAX * CAP];     // 51.2 MB bucketed adjacency

// ---------------------------------------------------------------------------
// Merged fill || convert, roles INTERLEAVED by blockIdx%3 (1 fill : 2 convert)
// so atomic-latency-bound fill blocks and BW-bound convert blocks coexist in
// every wave instead of running as two serial phases.
//   fill:    4 edges/thread, int4 batch loads -> 4 independent ATOMG chains
//   convert: 4 float4/thread (LDG.128 x4, __ldcs streaming) -> fp16 table
// ---------------------------------------------------------------------------
__global__ void k_fill_convert(const float* __restrict__ x,
                               const int* __restrict__ ei,
                               int total4, int E, int N, int BF) {
    int fid = blockIdx.x / 3;
    bool is_fill = ((blockIdx.x % 3) == 0) && (fid < BF);
    if (is_fill) {
        int t = fid * blockDim.x + threadIdx.x;
        int e0 = t * 4;
        if (e0 + 4 <= E) {
            int4 rows = __ldcs(reinterpret_cast<const int4*>(ei + e0));
            int4 cols = __ldcs(reinterpret_cast<const int4*>(ei + E + e0));
            int r[4] = { rows.x, rows.y, rows.z, rows.w };
            int c[4] = { cols.x, cols.y, cols.z, cols.w };
            #pragma unroll
            for (int q = 0; q < 4; q++) {
                if ((unsigned)r[q] < (unsigned)N && (unsigned)c[q] < (unsigned)N) {
                    int pos = atomicAdd(&g_cursor[r[q]], 1);
                    if (pos < CAP) g_csr[(size_t)r[q] * CAP + pos] = c[q];
                }
            }
        } else if (e0 < E) {
            for (int e = e0; e < E; e++) {
                int row = ei[e];
                int col = ei[E + e];
                if ((unsigned)row < (unsigned)N && (unsigned)col < (unsigned)N) {
                    int pos = atomicAdd(&g_cursor[row], 1);
                    if (pos < CAP) g_csr[(size_t)row * CAP + pos] = col;
                }
            }
        }
    } else {
        int cid = blockIdx.x - (blockIdx.x + 2) / 3;   // dense convert index
        int base = cid * (blockDim.x * 4) + threadIdx.x;
        const float4* xs = reinterpret_cast<const float4*>(x);
        uint2* dst = reinterpret_cast<uint2*>(g_xh);
        if (base + 768 < total4) {
            // full batch: unconditional, 4 streaming LDG.128 in flight
            float4 v0 = __ldcs(xs + base);
            float4 v1 = __ldcs(xs + base + 256);
            float4 v2 = __ldcs(xs + base + 512);
            float4 v3 = __ldcs(xs + base + 768);
            float4 v[4] = { v0, v1, v2, v3 };
            #pragma unroll
            for (int q = 0; q < 4; q++) {
                __half2 a = __floats2half2_rn(v[q].x, v[q].y);
                __half2 b = __floats2half2_rn(v[q].z, v[q].w);
                uint2 o;
                o.x = *reinterpret_cast<unsigned*>(&a);
                o.y = *reinterpret_cast<unsigned*>(&b);
                dst[base + q * 256] = o;
            }
        } else {
            #pragma unroll
            for (int q = 0; q < 4; q++) {
                int i = base + q * 256;
                if (i < total4) {
                    float4 v = __ldcs(xs + i);
                    __half2 a = __floats2half2_rn(v.x, v.y);
                    __half2 b = __floats2half2_rn(v.z, v.w);
                    uint2 o;
                    o.x = *reinterpret_cast<unsigned*>(&a);
                    o.y = *reinterpret_cast<unsigned*>(&b);
                    dst[i] = o;
                }
            }
        }
    }
}

// ---------------------------------------------------------------------------
// Gather-aggregate: half-warp per node, MLP-8 (unchanged; at L2 gather floor).
// Resets g_cursor[node] = 0 after reading (prepares next graph replay).
// ---------------------------------------------------------------------------
__device__ __forceinline__ __half2 slot_h2(const uint4& v, int s) {
    return *reinterpret_cast<const __half2*>(reinterpret_cast<const unsigned*>(&v.x) + s);
}

__global__ void k_aggregate(int N) {
    int node = (int)((blockIdx.x * blockDim.x + threadIdx.x) >> 4);
    if (node >= N) return;
    int hlane = threadIdx.x & 15;
    int deg  = g_cursor[node];
    if (deg > CAP) deg = CAP;
    const int* list = g_csr + node * CAP;

    const uint4* xh = reinterpret_cast<const uint4*>(g_xh);   // 16 uint4 / row
    float acc[8];
    #pragma unroll
    for (int s = 0; s < 8; s++) acc[s] = 0.f;

    int j = 0;
    for (; j + 8 <= deg; j += 8) {
        int4 ca = *reinterpret_cast<const int4*>(list + j);
        int4 cb = *reinterpret_cast<const int4*>(list + j + 4);
        uint4 v0 = xh[(unsigned)ca.x * 16u + (unsigned)hlane];
        uint4 v1 = xh[(unsigned)ca.y * 16u + (unsigned)hlane];
        uint4 v2 = xh[(unsigned)ca.z * 16u + (unsigned)hlane];
        uint4 v3 = xh[(unsigned)ca.w * 16u + (unsigned)hlane];
        uint4 v4 = xh[(unsigned)cb.x * 16u + (unsigned)hlane];
        uint4 v5 = xh[(unsigned)cb.y * 16u + (unsigned)hlane];
        uint4 v6 = xh[(unsigned)cb.z * 16u + (unsigned)hlane];
        uint4 v7 = xh[(unsigned)cb.w * 16u + (unsigned)hlane];
        #pragma unroll
        for (int s = 0; s < 4; s++) {
            __half2 ta = __hadd2(__hadd2(slot_h2(v0, s), slot_h2(v1, s)),
                                 __hadd2(slot_h2(v2, s), slot_h2(v3, s)));
            __half2 tb = __hadd2(__hadd2(slot_h2(v4, s), slot_h2(v5, s)),
                                 __hadd2(slot_h2(v6, s), slot_h2(v7, s)));
            float2 fa = __half22float2(ta);
            float2 fb = __half22float2(tb);
            acc[2 * s]     += fa.x + fb.x;
            acc[2 * s + 1] += fa.y + fb.y;
        }
    }
    for (; j + 4 <= deg; j += 4) {
        int4 cs = *reinterpret_cast<const int4*>(list + j);
        uint4 v0 = xh[(unsigned)cs.x * 16u + (unsigned)hlane];
        uint4 v1 = xh[(unsigned)cs.y * 16u + (unsigned)hlane];
        uint4 v2 = xh[(unsigned)cs.z * 16u + (unsigned)hlane];
        uint4 v3 = xh[(unsigned)cs.w * 16u + (unsigned)hlane];
        #pragma unroll
        for (int s = 0; s < 4; s++) {
            __half2 t = __hadd2(__hadd2(slot_h2(v0, s), slot_h2(v1, s)),
                                __hadd2(slot_h2(v2, s), slot_h2(v3, s)));
            float2 f = __half22float2(t);
            acc[2 * s]     += f.x;
            acc[2 * s + 1] += f.y;
        }
    }
    for (; j < deg; j++) {
        int c = list[j];
        uint4 v = xh[(unsigned)c * 16u + (unsigned)hlane];
        #pragma unroll
        for (int s = 0; s < 4; s++) {
            float2 f = __half22float2(slot_h2(v, s));
            acc[2 * s]     += f.x;
            acc[2 * s + 1] += f.y;
        }
    }

    uint4 o;
    unsigned* op = reinterpret_cast<unsigned*>(&o.x);
    #pragma unroll
    for (int s = 0; s < 4; s++) {
        __half2 h = __floats2half2_rn(acc[2 * s], acc[2 * s + 1]);
        op[s] = *reinterpret_cast<unsigned*>(&h);
    }
    reinterpret_cast<uint4*>(g_aggh)[(unsigned)node * 16u + (unsigned)hlane] = o;

    if (hlane == 0) g_cursor[node] = 0;   // ready for next replay
}

// ---------------------------------------------------------------------------
// Persistent FP16 tensor-core GEMM: cp.async pipeline, 512 threads,
// ldmatrix.x4 A-frags, pair-permuted B, __stcs epilogue (out never re-read,
// keeps g_xh/g_aggh L2-resident for later tiles' A reads).
// ---------------------------------------------------------------------------
#define SH_A 136
#define SH_W 272
#define SMEM_W_HALVES (128 * SH_W)   // 34816 halves = 69632 B
#define SMEM_A_HALVES (128 * SH_A)   // 17408 halves = 34816 B (per x/agg array)

__device__ __forceinline__ unsigned pack_h2(float a, float b) {
    __half2 h = __floats2half2_rn(a, b);
    return *reinterpret_cast<unsigned*>(&h);
}

__device__ __forceinline__ void mma_fp16(float d[4],
                                         const unsigned a[4],
                                         unsigned b0, unsigned b1) {
    asm volatile(
        "mma.sync.aligned.m16n8k16.row.col.f32.f16.f16.f32 "
        "{%0,%1,%2,%3},{%4,%5,%6,%7},{%8,%9},{%0,%1,%2,%3};"
        : "+f"(d[0]), "+f"(d[1]), "+f"(d[2]), "+f"(d[3])
        : "r"(a[0]), "r"(a[1]), "r"(a[2]), "r"(a[3]), "r"(b0), "r"(b1));
}

__device__ __forceinline__ void ldmatrix_x4(unsigned a[4], unsigned saddr) {
    asm volatile(
        "ldmatrix.sync.aligned.m8n8.x4.shared.b16 {%0,%1,%2,%3}, [%4];"
        : "=r"(a[0]), "=r"(a[1]), "=r"(a[2]), "=r"(a[3])
        : "r"(saddr));
}

__device__ __forceinline__ void cp_async16(__half* smem_dst, const void* gmem_src,
                                           bool valid) {
    unsigned saddr = (unsigned)__cvta_generic_to_shared(smem_dst);
    int sz = valid ? 16 : 0;
    asm volatile("cp.async.cg.shared.global [%0], [%1], 16, %2;\n"
                 :: "r"(saddr), "l"(gmem_src), "r"(sz));
}
__device__ __forceinline__ void cp_commit() {
    asm volatile("cp.async.commit_group;\n");
}
template <int NWAIT>
__device__ __forceinline__ void cp_wait() {
    asm volatile("cp.async.wait_group %0;\n" :: "n"(NWAIT));
}

__global__ void __launch_bounds__(512, 1)
k_mma_gemm(const float* __restrict__ W1,
           const float* __restrict__ W2,
           float* __restrict__ out, int N)
{
    extern __shared__ __half sm[];
    __half* sW = sm;                                   // [128][272] pair-permuted
    __half* sBuf0 = sW + SMEM_W_HALVES;                // buf0: x then agg
    __half* sBuf1 = sBuf0 + 2 * SMEM_A_HALVES;         // buf1: x then agg

    const int tid    = threadIdx.x;
    const int lane   = tid & 31;
    const int wid    = tid >> 5;     // 0..15
    const int gid    = lane >> 2;    // 0..7
    const int tig    = lane & 3;     // 0..3
    const int warp_m = wid & 3;      // rows 32*warp_m
    const int warp_n = wid >> 2;     // cols 32*warp_n (0..3)
    const int lrow   = lane & 15;    // ldmatrix row within 16
    const int lkoff  = (lane >> 4) << 3;  // ldmatrix k offset (0 or 8 halves)

    // ---- Stage weights ONCE (fp32 -> fp16, pair-permuted) ----
    {
        const float4* W1_4 = reinterpret_cast<const float4*>(W1);
        const float4* W2_4 = reinterpret_cast<const float4*>(W2);
        #pragma unroll
        for (int idx = tid; idx < 4096; idx += 512) {
            int mtx = idx >> 11;
            int n   = (idx >> 4) & 127;
            int g8  = idx & 15;
            const float4* src = mtx ? W2_4 : W1_4;
            float4 f0 = src[n * 32 + g8 * 2];
            float4 f1 = src[n * 32 + g8 * 2 + 1];
            int kg  = mtx * 128 + g8 * 8;
            int G   = kg >> 4;
            int odd = (kg >> 3) & 1;
            unsigned* dst = reinterpret_cast<unsigned*>(sW + n * SH_W + G * 16 + 2 * odd);
            dst[0] = pack_h2(f0.x, f0.y);
            dst[2] = pack_h2(f0.z, f0.w);
            dst[4] = pack_h2(f1.x, f1.y);
            dst[6] = pack_h2(f1.z, f1.w);
        }
    }

    const uint4* xh4 = reinterpret_cast<const uint4*>(g_xh);   // 16 uint4 / row
    const uint4* ah4 = reinterpret_cast<const uint4*>(g_aggh);
    const int ntiles = (N + 127) / 128;

    auto stage = [&](int tile, __half* buf) {
        int row0 = tile * 128;
        #pragma unroll
        for (int i = 0; i < 4; i++) {
            int idx = tid + i * 512;        // 2048 = 128 rows * 16 chunks
            int r   = idx >> 4;
            int g8  = idx & 15;
            int gr  = row0 + r;
            bool v  = (gr < N);
            int grc = v ? gr : 0;
            cp_async16(buf + r * SH_A + g8 * 8,
                       xh4 + (size_t)grc * 16 + g8, v);
            cp_async16(buf + SMEM_A_HALVES + r * SH_A + g8 * 8,
                       ah4 + (size_t)grc * 16 + g8, v);
        }
    };

    __half* bufs[2] = { sBuf0, sBuf1 };
    int t0 = blockIdx.x;
    if (t0 < ntiles) { stage(t0, bufs[0]); cp_commit(); }

    int b = 0;
    for (int tile = t0; tile < ntiles; tile += gridDim.x, b ^= 1) {
        int nxt = tile + gridDim.x;
        bool have_next = (nxt < ntiles);
        if (have_next) { stage(nxt, bufs[b ^ 1]); cp_commit(); }

        if (have_next) cp_wait<1>(); else cp_wait<0>();
        __syncthreads();

        const __half* bX  = bufs[b];
        const __half* bAg = bufs[b] + SMEM_A_HALVES;
        const int row0 = tile * 128;

        float d[2][4][4];
        #pragma unroll
        for (int m = 0; m < 2; m++)
            #pragma unroll
            for (int j = 0; j < 4; j++)
                #pragma unroll
                for (int q = 0; q < 4; q++)
                    d[m][j][q] = 0.f;

        #pragma unroll
        for (int ks = 0; ks < 16; ks++) {
            const __half* buf = (ks < 8) ? bX : bAg;
            const int k0 = (ks & 7) * 16;

            unsigned a[2][4];
            #pragma unroll
            for (int m = 0; m < 2; m++) {
                int rowA = warp_m * 32 + m * 16 + lrow;
                unsigned sa = (unsigned)__cvta_generic_to_shared(
                    buf + rowA * SH_A + k0 + lkoff);
                ldmatrix_x4(a[m], sa);
            }
            unsigned b0[4], b1[4];
            #pragma unroll
            for (int j = 0; j < 4; j++) {
                int n = warp_n * 32 + j * 8 + gid;
                uint2 w = reinterpret_cast<const uint2*>(sW + n * SH_W + ks * 16)[tig];
                b0[j] = w.x;
                b1[j] = w.y;
            }
            #pragma unroll
            for (int m = 0; m < 2; m++)
                #pragma unroll
                for (int j = 0; j < 4; j++)
                    mma_fp16(d[m][j], a[m], b0[j], b1[j]);
        }

        // ---- Epilogue: relu + streaming float2 stores ----
        #pragma unroll
        for (int m = 0; m < 2; m++) {
            int r = row0 + warp_m * 32 + m * 16 + gid;
            #pragma unroll
            for (int j = 0; j < 4; j++) {
                int cbase = warp_n * 32 + j * 8 + tig * 2;
                if (r < N) {
                    float2 o = make_float2(fmaxf(d[m][j][0], 0.f), fmaxf(d[m][j][1], 0.f));
                    __stcs(reinterpret_cast<float2*>(out + (size_t)r * 128 + cbase), o);
                }
                if (r + 8 < N) {
                    float2 o = make_float2(fmaxf(d[m][j][2], 0.f), fmaxf(d[m][j][3], 0.f));
                    __stcs(reinterpret_cast<float2*>(out + (size_t)(r + 8) * 128 + cbase), o);
                }
            }
        }
        __syncthreads();   // all warps done reading bufs[b] before restage
    }
}

// ---------------------------------------------------------------------------
// Launch
// ---------------------------------------------------------------------------
extern "C" void kernel_launch(void* const* d_in, const int* in_sizes, int n_in,
                              void* d_out, int out_size) {
    const float* x  = (const float*)d_in[0];
    const int*   ei = (const int*)d_in[1];
    const float* W1 = (const float*)d_in[2];
    const float* W2 = (const float*)d_in[3];
    float* out = (float*)d_out;

    int N = in_sizes[0] / DIMS;       // 100000
    int E = in_sizes[1] / 2;          // 1600000

    // fill || convert (roles interleaved by blockIdx%3: 1 fill : 2 convert)
    {
        int total4 = N * (DIMS / 4);                       // 3.2M float4
        int BF = ((E + 3) / 4 + 255) / 256;                // fill blocks (1563)
        int BC = (total4 + 1023) / 1024;                   // convert blocks (3125)
        k_fill_convert<<<BF + BC, 256>>>(x, ei, total4, E, N, BF);
    }

    // gather-aggregate (half-warp per node, MLP-8) + cursor reset
    {
        size_t threads = (size_t)N * 16;
        int blocks = (int)((threads + 255) / 256);
        k_aggregate<<<blocks, 256>>>(N);
    }

    // persistent fp16 tensor-core GEMM + relu (cp.async + ldmatrix, 512 thr)
    {
        int smem_bytes = (SMEM_W_HALVES + 4 * SMEM_A_HALVES) * (int)sizeof(__half); // 208896
        cudaFuncSetAttribute(k_mma_gemm,
                             cudaFuncAttributeMaxDynamicSharedMemorySize,
                             smem_bytes);
        k_mma_gemm<<<148, 512, smem_bytes>>>(W1, W2, out, N);
    }
}